// round 17
// baseline (speedup 1.0000x reference)
#include <cuda_runtime.h>
#include <cuda_fp16.h>
#include <cstdint>

#define N_TOKENS 16384
#define HIDDEN   4096
#define NE       192   // 3 * 64 experts
#define E        64
#define LOG2E    1.4426950408889634f
#define WSCALE   64.0f
#define INV_WSCALE (1.0f / 64.0f)

// ---------------- scratch ----------------------------------------------------
__device__ __half g_w[NE * HIDDEN];   // fp16(W * 64)

// ---------------- helpers ----------------------------------------------------
__device__ __forceinline__ uint32_t smem_u32(const void* p) {
    uint32_t a;
    asm("{ .reg .u64 t; cvta.to.shared.u64 t, %1; cvt.u32.u64 %0, t; }" : "=r"(a) : "l"(p));
    return a;
}
__device__ __forceinline__ void sts64(uint32_t addr, uint32_t a, uint32_t b) {
    asm volatile("st.shared.v2.b32 [%0], {%1, %2};" :: "r"(addr), "r"(a), "r"(b));
}
__device__ __forceinline__ void cp_async16(uint32_t dst, const void* src) {
    asm volatile("cp.async.cg.shared.global [%0], [%1], 16;" :: "r"(dst), "l"(src));
}
__device__ __forceinline__ void cp_commit() {
    asm volatile("cp.async.commit_group;" ::: "memory");
}
template <int N>
__device__ __forceinline__ void cp_wait() {
    asm volatile("cp.async.wait_group %0;" :: "n"(N) : "memory");
}
__device__ __forceinline__ void bar_sync(int id) {
    asm volatile("bar.sync %0, 256;" :: "r"(id) : "memory");
}
__device__ __forceinline__ void bar_arrive(int id) {
    asm volatile("bar.arrive %0, 256;" :: "r"(id) : "memory");
}
__device__ __forceinline__ void ldmatrix_x4(uint32_t* r, uint32_t addr) {
    asm volatile("ldmatrix.sync.aligned.m8n8.x4.shared.b16 {%0,%1,%2,%3}, [%4];"
                 : "=r"(r[0]), "=r"(r[1]), "=r"(r[2]), "=r"(r[3]) : "r"(addr));
}
__device__ __forceinline__ void mma_f16(float* d, const uint32_t* a, const uint32_t* b) {
    asm volatile(
        "mma.sync.aligned.m16n8k16.row.col.f32.f16.f16.f32 "
        "{%0,%1,%2,%3}, {%4,%5,%6,%7}, {%8,%9}, {%0,%1,%2,%3};"
        : "+f"(d[0]), "+f"(d[1]), "+f"(d[2]), "+f"(d[3])
        : "r"(a[0]), "r"(a[1]), "r"(a[2]), "r"(a[3]), "r"(b[0]), "r"(b[1]));
}
__device__ __forceinline__ float ex2_approx(float x) {
    float y;
    asm("ex2.approx.f32 %0, %1;" : "=f"(y) : "f"(x));
    return y;
}
__device__ __forceinline__ uint32_t pack_h2(float x0, float x1) {
    __half2 h = __floats2half2_rn(x0, x1);
    return *reinterpret_cast<uint32_t*>(&h);
}
// XOR swizzle for 128B-pitch rows (conflict-free ldmatrix, 8B-aligned cbyte)
__device__ __forceinline__ uint32_t swz(uint32_t r, uint32_t cbyte) {
    return r * 128 + (cbyte ^ ((r & 7) << 4));
}

// ---------------- kernel 1: W*64 -> fp16 --------------------------------------
__global__ void prep_w_kernel(const float* __restrict__ W) {
    int i = blockIdx.x * blockDim.x + threadIdx.x;   // float4 index
    float4 v = reinterpret_cast<const float4*>(W)[i];
    uint32_t h01 = pack_h2(v.x * WSCALE, v.y * WSCALE);
    uint32_t h23 = pack_h2(v.z * WSCALE, v.w * WSCALE);
    reinterpret_cast<uint2*>(g_w)[i] = make_uint2(h01, h23);
}

// ---------------- fused GEMM + softmax-attention (warp-specialized) ----------
// mix = fp16(A) @ fp16(W*64)^T / 64  -- single MMA term.
// CTA: 64 tokens x 192 cols, BK=64, 2 CTAs per SM (independent pipelines
// interleave: one CTA's MMAs fill the other's LDSM/barrier/epilogue bubbles).
// 256 threads:
//   warps 0-5 = consumers (2M x 3N, warp tile 32x64): LDSM + MMA only,
//               h-steps rotated per warp to de-phase LDSM bursts
//   warps 6-7 = producers: A LDG->fp16->STS (LDG pipelined 1 period ahead),
//               B cp.async (3-slot, 2 periods ahead)
static constexpr int NSTEP     = HIDDEN / 64;     // 64 barrier periods
static constexpr int A_STAGE   = 64 * 128;        // 8192 (64 rows x 128B)
static constexpr int B_OFF     = 2 * A_STAGE;     // 16384
static constexpr int B_STAGE   = 192 * 128;       // 24576
static constexpr int GEMM_SMEM = B_OFF + 3 * B_STAGE;  // 90112
static constexpr int Q2_OFF    = 0;                     // 64*65*4 = 16640
static constexpr int KV_OFF    = 16640;                 // 64*66*8 = 33792

// named barrier ids: FULL = 1 + (k&1), FREE = 3 + (k&1)
__global__ void __launch_bounds__(256, 2)
gemm_fused_kernel(const float* __restrict__ A, float* __restrict__ out) {
    extern __shared__ char smem[];
    const uint32_t sb  = smem_u32(smem);
    const int tid   = threadIdx.x;
    const int wid   = tid >> 5;
    const int lid   = tid & 31;
    const int mbase = blockIdx.x * 64;
    const bool consumer = (wid < 6);

    float acc[2][8][4];
    #pragma unroll
    for (int mt = 0; mt < 2; ++mt)
        #pragma unroll
        for (int n = 0; n < 8; ++n)
            #pragma unroll
            for (int j = 0; j < 4; ++j) acc[mt][n][j] = 0.f;

    const int m0 = (wid & 1) * 32;    // consumer M offset (2 groups)
    const int n0 = (wid >> 1) * 64;   // consumer N offset (3 groups)

    // consumer ldmatrix lane addressing
    const uint32_t a_lrow = (uint32_t)(m0 + (lid & 15));
    const uint32_t a_lcol = (uint32_t)(((lid >> 4) & 1) * 16);
    const uint32_t b_lrow = (uint32_t)(n0 + (lid & 7) + ((lid >> 4) & 1) * 8);
    const uint32_t b_lcol = (uint32_t)(((lid >> 3) & 1) * 16);

    if (consumer) {
        // ============================ CONSUMER ============================
        uint32_t af[2][2][4], bf[2][4][4];   // double-buffered fragments
        const int hoff = wid & 3;            // per-warp h-rotation (de-phase)

        auto load_frags = [&](uint32_t aST, uint32_t bST, int h, int buf) {
            #pragma unroll
            for (int mt = 0; mt < 2; ++mt)
                ldmatrix_x4(af[buf][mt],
                            aST + swz(a_lrow + mt * 16, a_lcol + h * 32));
            #pragma unroll
            for (int g = 0; g < 4; ++g)
                ldmatrix_x4(bf[buf][g],
                            bST + swz(b_lrow + g * 16, b_lcol + h * 32));
        };

        for (int kt = 0; kt < NSTEP; ++kt) {
            bar_sync(1 + (kt & 1));          // wait FULL(kt)
            bar_arrive(3 + ((kt + 1) & 1));  // release buffers of kt-1
            const uint32_t aST = sb + (kt & 1) * A_STAGE;
            const uint32_t bST = sb + B_OFF + (kt % 3) * B_STAGE;
            load_frags(aST, bST, hoff, 0);
            #pragma unroll
            for (int i = 0; i < 4; ++i) {
                const int cur = i & 1;
                if (i < 3)
                    load_frags(aST, bST, (i + 1 + hoff) & 3, cur ^ 1);
                // 16 independent MMAs on current buffer
                #pragma unroll
                for (int mt = 0; mt < 2; ++mt)
                    #pragma unroll
                    for (int n = 0; n < 8; ++n)
                        mma_f16(acc[mt][n], af[cur][mt],
                                bf[cur][n >> 1] + (n & 1) * 2);
            }
        }
    } else {
        // ============================ PRODUCER ============================
        const int pt = tid - 192;   // 0..63, handles A row pt
        float4 va[16];              // one full A row (64 f32) staged

        // B cp.async for period kt into slot kt%3 (24 chunks per thread)
        auto cp_b = [&](int kt) {
            const uint32_t st = sb + B_OFF + (kt % 3) * B_STAGE;
            const char* wp = reinterpret_cast<const char*>(g_w);
            #pragma unroll
            for (int i = 0; i < 24; ++i) {
                int idx = pt + i * 64;            // 0..1535
                int r = idx >> 3;                 // row 0..191
                uint32_t cbyte = (uint32_t)(idx & 7) * 16;
                uint32_t dst = st + swz((uint32_t)r, cbyte);
                size_t soff = (size_t)r * (HIDDEN * 2) + (size_t)kt * 128 + cbyte;
                cp_async16(dst, wp + soff);
            }
        };
        // issue A LDGs for period kt (row pt, 16 float4)
        auto g2r_a = [&](int kt) {
            const float4* Ag = reinterpret_cast<const float4*>(A) +
                               (size_t)(mbase + pt) * (HIDDEN / 4) + kt * 16;
            #pragma unroll
            for (int i = 0; i < 16; ++i)
                va[i] = Ag[i];
        };
        // convert va -> fp16, store into A slot kt&1
        auto r2s_a = [&](int kt) {
            const uint32_t st = sb + (kt & 1) * A_STAGE;
            #pragma unroll
            for (int i = 0; i < 16; ++i) {
                uint32_t h01 = pack_h2(va[i].x, va[i].y);
                uint32_t h23 = pack_h2(va[i].z, va[i].w);
                uint32_t off = swz((uint32_t)pt, (uint32_t)(i * 8));
                sts64(st + off, h01, h23);
            }
        };

        // prologue: B(0),B(1) in flight; A(0) stored; A(1) preloaded
        cp_b(0); cp_commit();
        cp_b(1); cp_commit();
        g2r_a(0); r2s_a(0);
        g2r_a(1);              // preload next period's A (latency spans a period)
        cp_wait<1>();          // B(0) complete
        bar_arrive(1 + 0);     // FULL(0)

        for (int kt = 0; kt < NSTEP - 1; ++kt) {
            bar_sync(3 + ((kt + 1) & 1));    // FREE: slot (kt+1) writable
            r2s_a(kt + 1);                   // store preloaded A (no LDG wait)
            if (kt + 2 < NSTEP) {
                cp_b(kt + 2); cp_commit();
                g2r_a(kt + 2);               // next A LDGs; ~1 period in flight
                cp_wait<1>();
            } else {
                cp_wait<0>();
            }
            bar_arrive(1 + ((kt + 1) & 1));  // FULL(kt+1)
        }
    }

    __syncthreads();   // all compute done; smem stages free for reuse

    // ---- scatter mix tile into reused smem (undo WSCALE here) ----
    float* q2  = reinterpret_cast<float*>(smem + Q2_OFF);   // [64][65]
    float* kvf = reinterpret_cast<float*>(smem + KV_OFF);   // [64][66] float2
    if (consumer) {
        const int d_row = lid >> 2, d_col = (lid & 3) * 2;
        #pragma unroll
        for (int mt = 0; mt < 2; ++mt) {
            #pragma unroll
            for (int n = 0; n < 8; ++n) {
                int t = m0 + mt * 16 + d_row;
                int c = n0 + n * 8 + d_col;
                #pragma unroll
                for (int j = 0; j < 4; ++j) {
                    int tt = t + (j >> 1) * 8;
                    int cc = c + (j & 1);
                    float v = acc[mt][n][j] * INV_WSCALE;
                    if (cc < 64)       q2[tt * 65 + cc] = v * LOG2E;
                    else if (cc < 128) kvf[(tt * 66 + cc - 64) * 2]      = v;
                    else               kvf[(tt * 66 + cc - 128) * 2 + 1] = v;
                }
            }
        }
    }
    __syncthreads();

    // ---- fused epilogue: per-token softmax attention (4 threads/token) ----
    const int token = tid >> 2;   // 0..63
    const int g     = tid & 3;    // each owns 16 experts
    const float2* kvt = reinterpret_cast<const float2*>(kvf) + token * 66;
    const float*  q2t = q2 + token * 65;
    float* outt = out + (size_t)(mbase + token) * E;

    #pragma unroll 1
    for (int ei = 0; ei < 16; ei += 2) {
        int e0 = g * 16 + ei;
        float qa = q2t[e0], qb = q2t[e0 + 1];
        float Za = 0.f, Zb = 0.f, Sa = 0.f, Sb = 0.f;
        #pragma unroll 16
        for (int f = 0; f < E; ++f) {
            float2 p = kvt[f];
            float ta = ex2_approx(qa * p.x);
            float tb = ex2_approx(qb * p.x);
            Za += ta; Sa = fmaf(ta, p.y, Sa);
            Zb += tb; Sb = fmaf(tb, p.y, Sb);
        }
        outt[e0]     = __fdividef(Sa, Za);
        outt[e0 + 1] = __fdividef(Sb, Zb);
    }
}

// ---------------- launch -----------------------------------------------------
extern "C" void kernel_launch(void* const* d_in, const int* in_sizes, int n_in,
                              void* d_out, int out_size) {
    const float* hidden = (const float*)d_in[0];   // [16384, 4096] f32
    const float* W      = (const float*)d_in[1];   // [192, 4096]  f32
    float* out          = (float*)d_out;           // [16384, 64]  f32

    cudaFuncSetAttribute(gemm_fused_kernel,
                         cudaFuncAttributeMaxDynamicSharedMemorySize, GEMM_SMEM);

    prep_w_kernel<<<(NE * HIDDEN / 4) / 256, 256>>>(W);
    gemm_fused_kernel<<<N_TOKENS / 64, 256, GEMM_SMEM>>>(hidden, out);
}